// round 3
// baseline (speedup 1.0000x reference)
#include <cuda_runtime.h>
#include <math.h>

#define MDIM 4096
#define NT 32            // 32 tile-rows of 128
#define TILE 128
#define NTILES 528       // upper triangle: 32*33/2
#define B1f 0.9f
#define B2f 0.999f
#define EPSV 1e-8f
#define LRV 0.1f
#define NSTEPS 199

// ---- scratch (__device__ globals; no allocation) ----
__device__ float d_Qs[(size_t)MDIM * MDIM];      // 64 MB symmetrized fp32
__device__ float d_g[(NSTEPS + 1)][MDIM];        // per-step gradient buffers (g[0] stays 0)
__device__ float d_W[2][MDIM];                    // parity-buffered Adam state
__device__ float d_MT[2][MDIM];
__device__ float d_VT[2][MDIM];

// ---------------------------------------------------------------------------
// Qs = 0.5*(va + va^T)  (full matrix; only upper tiles are read later)
// ---------------------------------------------------------------------------
__global__ void prep_qs_kernel(const float* __restrict__ va) {
    __shared__ float tile[32][33];
    int bx = blockIdx.x * 32, by = blockIdx.y * 32;
    int tx = threadIdx.x, ty = threadIdx.y;
    tile[ty][tx] = va[(size_t)(bx + ty) * MDIM + (by + tx)];
    __syncthreads();
    size_t idx = (size_t)(by + ty) * MDIM + (bx + tx);
    d_Qs[idx] = 0.5f * (va[idx] + tile[tx][ty]);
}

// ---------------------------------------------------------------------------
// Init: state parity0 (w=1, mt=vt=0) and zero ALL g buffers (replay-safe).
// ---------------------------------------------------------------------------
__global__ void init_kernel() {
    int i = blockIdx.x * blockDim.x + threadIdx.x;
    if (i < MDIM) {
        d_W[0][i] = 1.0f;  d_W[1][i] = 1.0f;
        d_MT[0][i] = 0.0f; d_MT[1][i] = 0.0f;
        d_VT[0][i] = 0.0f; d_VT[1][i] = 0.0f;
    }
    // zero g buffers: (NSTEPS+1)*MDIM floats
    int total = (NSTEPS + 1) * MDIM;
    for (int j = i; j < total; j += gridDim.x * blockDim.x)
        (&d_g[0][0])[j] = 0.0f;
}

// ---------------------------------------------------------------------------
// Launch s (s=1..199):
//   prologue: Adam step (s-1) for the <=256 rows this block needs
//             (duplicate deterministic writes, parity p -> q), build x in smem
//   body:     SYMV tile contribution -> atomicAdd into d_g[s]
// ---------------------------------------------------------------------------
__global__ __launch_bounds__(256)
void symv_step_kernel(const float* __restrict__ mean,
                      const float* __restrict__ g_prev,   // d_g[s-1]
                      float* __restrict__ g_out,          // d_g[s]
                      int p,                              // read parity
                      float step_lr,                      // LR/bc1 for step s-1 (0 if s==1)
                      float inv_sqrt_bc2)                 // 1/sqrt(bc2) for step s-1
{
    __shared__ float xs[2 * TILE];     // [0..127] = x_I, [128..255] = x_J
    __shared__ float gi[TILE];
    __shared__ float gj[TILE];

    // --- map block -> upper-triangle tile (ti <= tj) ---
    int b = blockIdx.x;
    int ti = 0, rem = b;
    while (rem >= NT - ti) { rem -= NT - ti; ++ti; }
    int tj = ti + rem;
    const int I = ti * TILE, J = tj * TILE;
    const bool diag = (ti == tj);

    int tid = threadIdx.x;
    int q = p ^ 1;

    // --- prologue: Adam update for needed rows, build xs ---
    if (tid < TILE) { gi[tid] = 0.0f; gj[tid] = 0.0f; }
    {
        int row = -1;
        if (diag) { if (tid < TILE) row = I + tid; }
        else      { row = (tid < TILE) ? (I + tid) : (J + tid - TILE); }
        if (row >= 0) {
            float g  = g_prev[row];
            float wp = d_W[p][row];
            float mt = B1f * d_MT[p][row] + (1.0f - B1f) * g;
            float vt = B2f * d_VT[p][row] + (1.0f - B2f) * g * g;
            float wn = wp - step_lr * mt / (sqrtf(vt) * inv_sqrt_bc2 + EPSV);
            d_W[q][row]  = wn;
            d_MT[q][row] = mt;
            d_VT[q][row] = vt;
            float x = wn - mean[row];
            xs[tid] = x;
            if (diag) xs[TILE + tid] = x;   // x_J == x_I on diagonal
        }
    }
    __syncthreads();

    // --- tile SYMV: 8 warps x 16 rows; one float4 per lane per row ---
    int warp = tid >> 5, lane = tid & 31;
    const float4* __restrict__ Q4 = reinterpret_cast<const float4*>(d_Qs);
    const float4* __restrict__ xj4 = reinterpret_cast<const float4*>(xs + TILE);

    float4 xj = xj4[lane];
    float colacc0 = 0.f, colacc1 = 0.f, colacc2 = 0.f, colacc3 = 0.f;

    #pragma unroll 4
    for (int r16 = 0; r16 < 16; ++r16) {
        int r = warp * 16 + r16;
        float4 qv = Q4[(size_t)(I + r) * (MDIM / 4) + (J / 4) + lane];
        // row dot: g[I+r] += sum_c Q[I+r][J+c] * x[J+c]
        float rd = qv.x * xj.x + qv.y * xj.y + qv.z * xj.z + qv.w * xj.w;
        #pragma unroll
        for (int off = 16; off > 0; off >>= 1)
            rd += __shfl_xor_sync(0xFFFFFFFFu, rd, off);
        if (lane == 0) gi[r] = rd;          // row r owned by exactly one warp? no:
        // NOTE: each warp owns distinct rows r = warp*16 + r16, so plain store OK
        if (!diag) {
            float xi = xs[r];
            colacc0 = fmaf(qv.x, xi, colacc0);
            colacc1 = fmaf(qv.y, xi, colacc1);
            colacc2 = fmaf(qv.z, xi, colacc2);
            colacc3 = fmaf(qv.w, xi, colacc3);
        }
    }
    if (!diag) {
        atomicAdd(&gj[4 * lane + 0], colacc0);
        atomicAdd(&gj[4 * lane + 1], colacc1);
        atomicAdd(&gj[4 * lane + 2], colacc2);
        atomicAdd(&gj[4 * lane + 3], colacc3);
    }
    __syncthreads();

    // --- flush to global g ---
    if (tid < TILE) {
        atomicAdd(&g_out[I + tid], gi[tid]);
        if (!diag) atomicAdd(&g_out[J + tid], gj[tid]);
    }
}

// ---------------------------------------------------------------------------
// Finish: apply Adam step 199 -> d_out
// ---------------------------------------------------------------------------
__global__ void finish_kernel(float* __restrict__ out,
                              const float* __restrict__ g_last,
                              int p, float step_lr, float inv_sqrt_bc2) {
    int i = blockIdx.x * blockDim.x + threadIdx.x;
    if (i < MDIM) {
        float g  = g_last[i];
        float mt = B1f * d_MT[p][i] + (1.0f - B1f) * g;
        float vt = B2f * d_VT[p][i] + (1.0f - B2f) * g * g;
        out[i] = d_W[p][i] - step_lr * mt / (sqrtf(vt) * inv_sqrt_bc2 + EPSV);
    }
}

// ---------------------------------------------------------------------------
extern "C" void kernel_launch(void* const* d_in, const int* in_sizes, int n_in,
                              void* d_out, int out_size) {
    const float* mean = (const float*)d_in[0];
    const float* va   = (const float*)d_in[1];
    float* out = (float*)d_out;
    (void)in_sizes; (void)n_in; (void)out_size;

    float* g_base; cudaGetSymbolAddress((void**)&g_base, d_g);

    dim3 tb(32, 32), tg(MDIM / 32, MDIM / 32);
    prep_qs_kernel<<<tg, tb>>>(va);
    init_kernel<<<64, 256>>>();

    // launches s = 1..199; prologue applies Adam step (s-1)
    for (int s = 1; s <= NSTEPS; ++s) {
        int t = s - 1;                       // Adam step applied in prologue
        float step_lr = 0.f, inv_b2 = 0.f;
        if (t >= 1) {
            double bc1 = 1.0 - pow((double)B1f, (double)t);
            double bc2 = 1.0 - pow((double)B2f, (double)t);
            step_lr = (float)((double)LRV / bc1);
            inv_b2  = (float)(1.0 / sqrt(bc2));
        }
        int p = (s - 1) & 1;                 // read parity
        symv_step_kernel<<<NTILES, 256>>>(mean,
                                          g_base + (size_t)(s - 1) * MDIM,
                                          g_base + (size_t)s * MDIM,
                                          p, step_lr, inv_b2);
    }

    // final Adam step t=199 (state parity written by launch 199 is q=199&1=1)
    {
        int t = NSTEPS;
        double bc1 = 1.0 - pow((double)B1f, (double)t);
        double bc2 = 1.0 - pow((double)B2f, (double)t);
        float step_lr = (float)((double)LRV / bc1);
        float inv_b2  = (float)(1.0 / sqrt(bc2));
        finish_kernel<<<(MDIM + 255) / 256, 256>>>(out,
                                                   g_base + (size_t)NSTEPS * MDIM,
                                                   NSTEPS & 1, step_lr, inv_b2);
    }
}

// round 4
// speedup vs baseline: 1.4170x; 1.4170x over previous
#include <cuda_runtime.h>
#include <math.h>

#define MDIM 4096
#define NT 32            // 32 tile-rows of 128
#define TILE 128
#define NTILES 528       // upper triangle: 32*33/2
#define B1f 0.9f
#define B2f 0.999f
#define EPSV 1e-8f
#define LRV 0.1f
#define NSTEPS 199

// ---- scratch (__device__ globals; no allocation) ----
__device__ float d_Qs[(size_t)MDIM * MDIM];      // symmetrized fp32 (upper half valid)
__device__ float d_g[(NSTEPS + 1)][MDIM];        // per-step gradient buffers (g[0] stays 0)
__device__ float d_W[2][MDIM];                   // parity-buffered Adam state
__device__ float d_MT[2][MDIM];
__device__ float d_VT[2][MDIM];

// ---------------------------------------------------------------------------
// Qs = 0.5*(va + va^T), upper-triangle blocks only.
// ---------------------------------------------------------------------------
__global__ void prep_qs_kernel(const float* __restrict__ va) {
    __shared__ float tile[32][33];
    int bx = blockIdx.x * 32, by = blockIdx.y * 32;   // by = row block, bx = col block
    if (bx + 32 <= by) return;                        // only col-end > row-start (upper)
    int tx = threadIdx.x, ty = threadIdx.y;
    tile[ty][tx] = va[(size_t)(bx + ty) * MDIM + (by + tx)];
    __syncthreads();
    size_t idx = (size_t)(by + ty) * MDIM + (bx + tx);
    d_Qs[idx] = 0.5f * (va[idx] + tile[tx][ty]);
}

// ---------------------------------------------------------------------------
// Init: state parity0/1 and zero ALL g buffers (replay-safe).
// ---------------------------------------------------------------------------
__global__ void init_kernel() {
    int i = blockIdx.x * blockDim.x + threadIdx.x;
    if (i < MDIM) {
        d_W[0][i] = 1.0f;  d_W[1][i] = 1.0f;
        d_MT[0][i] = 0.0f; d_MT[1][i] = 0.0f;
        d_VT[0][i] = 0.0f; d_VT[1][i] = 0.0f;
    }
    int total = (NSTEPS + 1) * MDIM;
    for (int j = i; j < total; j += gridDim.x * blockDim.x)
        (&d_g[0][0])[j] = 0.0f;
}

// ---------------------------------------------------------------------------
// Launch s: fused Adam prologue (step s-1) + upper-triangle SYMV tile.
// No cross-lane ops in the load stream; reductions deferred to smem pass.
// ---------------------------------------------------------------------------
__global__ __launch_bounds__(256)
void symv_step_kernel(const float* __restrict__ mean,
                      const float* __restrict__ g_prev,
                      float* __restrict__ g_out,
                      int p, float step_lr, float inv_sqrt_bc2)
{
    __shared__ float xsI[TILE];
    __shared__ float xsJ[TILE];
    __shared__ float part[TILE][33];   // row partials: [local row][lane]
    __shared__ float colp[8][TILE];    // col partials per warp

    // map block -> upper-triangle tile (ti <= tj)
    int b = blockIdx.x;
    int ti = 0, rem = b;
    while (rem >= NT - ti) { rem -= NT - ti; ++ti; }
    int tj = ti + rem;
    const int I = ti * TILE, J = tj * TILE;
    const bool diag = (ti == tj);

    int tid = threadIdx.x;
    int q = p ^ 1;

    // ---- prologue: Adam update (duplicated, deterministic) + build x ----
    {
        int row = -1;
        if (diag) { if (tid < TILE) row = I + tid; }
        else      { row = (tid < TILE) ? (I + tid) : (J + tid - TILE); }
        if (row >= 0) {
            float g  = g_prev[row];
            float mt = B1f * d_MT[p][row] + (1.0f - B1f) * g;
            float vt = B2f * d_VT[p][row] + (1.0f - B2f) * g * g;
            float wn = d_W[p][row] - step_lr * mt / (sqrtf(vt) * inv_sqrt_bc2 + EPSV);
            d_W[q][row]  = wn;
            d_MT[q][row] = mt;
            d_VT[q][row] = vt;
            float x = wn - mean[row];
            if (tid < TILE) { xsI[tid] = x; if (diag) xsJ[tid] = x; }
            else            { xsJ[tid - TILE] = x; }
        }
    }
    __syncthreads();

    // ---- main: warp owns 16 rows; lane owns one float4 col chunk ----
    int warp = tid >> 5, lane = tid & 31;
    const float4* __restrict__ Q4 = reinterpret_cast<const float4*>(d_Qs);
    float4 xj = reinterpret_cast<const float4*>(xsJ)[lane];   // loop-invariant

    size_t base = (size_t)(I + warp * 16) * (MDIM / 4) + (J / 4) + lane;
    float  rp[16];
    float4 ca = make_float4(0.f, 0.f, 0.f, 0.f);

    if (!diag) {
        #pragma unroll
        for (int rr = 0; rr < 16; rr += 8) {
            float4 qv[8];
            #pragma unroll
            for (int k = 0; k < 8; ++k)
                qv[k] = Q4[base + (size_t)(rr + k) * (MDIM / 4)];
            #pragma unroll
            for (int k = 0; k < 8; ++k) {
                float xi = xsI[warp * 16 + rr + k];
                rp[rr + k] = qv[k].x * xj.x + qv[k].y * xj.y
                           + qv[k].z * xj.z + qv[k].w * xj.w;
                ca.x = fmaf(qv[k].x, xi, ca.x);
                ca.y = fmaf(qv[k].y, xi, ca.y);
                ca.z = fmaf(qv[k].z, xi, ca.z);
                ca.w = fmaf(qv[k].w, xi, ca.w);
            }
        }
    } else {
        int c0 = 4 * lane;
        #pragma unroll
        for (int rr = 0; rr < 16; rr += 8) {
            float4 qv[8];
            #pragma unroll
            for (int k = 0; k < 8; ++k)
                qv[k] = Q4[base + (size_t)(rr + k) * (MDIM / 4)];
            #pragma unroll
            for (int k = 0; k < 8; ++k) {
                int lr = warp * 16 + rr + k;
                float xi = xsI[lr];
                // row part: include cols c >= lr
                float r0 = (c0 + 0 >= lr) ? qv[k].x * xj.x : 0.f;
                float r1 = (c0 + 1 >= lr) ? qv[k].y * xj.y : 0.f;
                float r2 = (c0 + 2 >= lr) ? qv[k].z * xj.z : 0.f;
                float r3 = (c0 + 3 >= lr) ? qv[k].w * xj.w : 0.f;
                rp[rr + k] = (r0 + r1) + (r2 + r3);
                // mirror (col) part: include cols c > lr
                if (c0 + 0 > lr) ca.x = fmaf(qv[k].x, xi, ca.x);
                if (c0 + 1 > lr) ca.y = fmaf(qv[k].y, xi, ca.y);
                if (c0 + 2 > lr) ca.z = fmaf(qv[k].z, xi, ca.z);
                if (c0 + 3 > lr) ca.w = fmaf(qv[k].w, xi, ca.w);
            }
        }
    }

    // deferred reductions: dump partials to smem
    #pragma unroll
    for (int k = 0; k < 16; ++k)
        part[warp * 16 + k][lane] = rp[k];
    reinterpret_cast<float4*>(colp[warp])[lane] = ca;
    __syncthreads();

    // ---- reduce + global atomic flush ----
    if (tid < TILE) {
        float s = 0.f;
        #pragma unroll
        for (int l = 0; l < 32; ++l) s += part[tid][l];
        atomicAdd(&g_out[I + tid], s);
    } else {
        int c = tid - TILE;
        float s = 0.f;
        #pragma unroll
        for (int w = 0; w < 8; ++w) s += colp[w][c];
        atomicAdd(&g_out[J + c], s);
    }
}

// ---------------------------------------------------------------------------
// Finish: apply Adam step 199 -> d_out
// ---------------------------------------------------------------------------
__global__ void finish_kernel(float* __restrict__ out,
                              const float* __restrict__ g_last,
                              int p, float step_lr, float inv_sqrt_bc2) {
    int i = blockIdx.x * blockDim.x + threadIdx.x;
    if (i < MDIM) {
        float g  = g_last[i];
        float mt = B1f * d_MT[p][i] + (1.0f - B1f) * g;
        float vt = B2f * d_VT[p][i] + (1.0f - B2f) * g * g;
        out[i] = d_W[p][i] - step_lr * mt / (sqrtf(vt) * inv_sqrt_bc2 + EPSV);
    }
}

// ---------------------------------------------------------------------------
extern "C" void kernel_launch(void* const* d_in, const int* in_sizes, int n_in,
                              void* d_out, int out_size) {
    const float* mean = (const float*)d_in[0];
    const float* va   = (const float*)d_in[1];
    float* out = (float*)d_out;
    (void)in_sizes; (void)n_in; (void)out_size;

    float* g_base; cudaGetSymbolAddress((void**)&g_base, d_g);

    dim3 tb(32, 32), tg(MDIM / 32, MDIM / 32);
    prep_qs_kernel<<<tg, tb>>>(va);
    init_kernel<<<128, 256>>>();

    for (int s = 1; s <= NSTEPS; ++s) {
        int t = s - 1;
        float step_lr = 0.f, inv_b2 = 0.f;
        if (t >= 1) {
            double bc1 = 1.0 - pow((double)B1f, (double)t);
            double bc2 = 1.0 - pow((double)B2f, (double)t);
            step_lr = (float)((double)LRV / bc1);
            inv_b2  = (float)(1.0 / sqrt(bc2));
        }
        int p = (s - 1) & 1;
        symv_step_kernel<<<NTILES, 256>>>(mean,
                                          g_base + (size_t)(s - 1) * MDIM,
                                          g_base + (size_t)s * MDIM,
                                          p, step_lr, inv_b2);
    }

    {
        int t = NSTEPS;
        double bc1 = 1.0 - pow((double)B1f, (double)t);
        double bc2 = 1.0 - pow((double)B2f, (double)t);
        float step_lr = (float)((double)LRV / bc1);
        float inv_b2  = (float)(1.0 / sqrt(bc2));
        finish_kernel<<<(MDIM + 255) / 256, 256>>>(out,
                                                   g_base + (size_t)NSTEPS * MDIM,
                                                   NSTEPS & 1, step_lr, inv_b2);
    }
}